// round 12
// baseline (speedup 1.0000x reference)
#include <cuda_runtime.h>
#include <cstdint>

// CausalDAG fused persistent kernel for GB300 (sm_103a). R12.
//   m = A^T x (exact fp32 fma2, emitted as bf16 hi/lo pairs)
//   h = elu(W1_c @ m + b1); out = W2_c @ h + b2   (bf16 m16n8k16, 3-mma comp)
//
// vs R8/R11: NO warp specialization. All 16 warps run both the mix (warp =
// batch row, lane = float2 chunk) and the MLP (warp = concept) for 16-row
// tiles, software-pipelined over a 2-buffer ring with ONE __syncthreads per
// tile. Mixed per-warp instruction streams (fma + HMMA + LDS + LDG) let the
// scheduler fill issue slots from whichever pipe is free, instead of the
// specialized design where each role idled while the other's burst ran.

#define Cc 16
#define Dd 64
#define Gg 32
#define NTH 512
#define ROWU2 36            // uint2 (hi,lo) pairs per row incl. pad -> conflict-free
#define CTU2 (16 * ROWU2)   // uint2 per concept block = 576
#define TILEU2 (Cc * CTU2)  // 9216 uint2 = 73728 B per tile buffer

typedef unsigned long long ull;

// Prepacked bf16 hi/lo weight fragments (same layout as R8).
// W1pk[((c*4+kt)*4+q)*32+lane], q: 0=hi(nt0,nt1) 1=hi(nt2,nt3) 2=lo(nt0,nt1) 3=lo(nt2,nt3)
// W2pk[((c*8+nt)*2+hl)*32+lane], uint4 = {b0(kt0),b1(kt0),b0(kt1),b1(kt1)}
__device__ uint4 W1pk[Cc * 4 * 4 * 32];
__device__ uint4 W2pk[Cc * 8 * 2 * 32];

__device__ __forceinline__ ull fma2(ull a, ull b, ull c) {
    ull d;
    asm("fma.rn.f32x2 %0, %1, %2, %3;" : "=l"(d) : "l"(a), "l"(b), "l"(c));
    return d;
}
__device__ __forceinline__ ull dup2(float a) {
    ull d;
    asm("mov.b64 %0, {%1, %1};" : "=l"(d) : "f"(a));
    return d;
}
// pack two f32 -> bf16x2, first arg lands in lower 16 bits
__device__ __forceinline__ uint32_t pack_bf16_2(float lo, float hi) {
    uint32_t r;
    asm("cvt.rn.bf16x2.f32 %0, %1, %2;" : "=r"(r) : "f"(hi), "f"(lo));
    return r;
}
// fp32 pair -> bf16 hi pair + bf16 lo pair (residual)
__device__ __forceinline__ void split_pair(float f0, float f1,
                                           uint32_t& hi, uint32_t& lo) {
    hi = pack_bf16_2(f0, f1);
    float f0h = __uint_as_float(hi << 16);
    float f1h = __uint_as_float(hi & 0xffff0000u);
    lo = pack_bf16_2(f0 - f0h, f1 - f1h);
}
__device__ __forceinline__ void mma_bf16(float c[4],
                                         uint32_t a0, uint32_t a1, uint32_t a2, uint32_t a3,
                                         uint32_t b0, uint32_t b1) {
    asm volatile(
        "mma.sync.aligned.m16n8k16.row.col.f32.bf16.bf16.f32 "
        "{%0,%1,%2,%3}, {%4,%5,%6,%7}, {%8,%9}, {%0,%1,%2,%3};"
        : "+f"(c[0]), "+f"(c[1]), "+f"(c[2]), "+f"(c[3])
        : "r"(a0), "r"(a1), "r"(a2), "r"(a3), "r"(b0), "r"(b1));
}
__device__ __forceinline__ float elu1(float v) {
    return v > 0.0f ? v : (__expf(v) - 1.0f);
}

// ---------------- Prep: pack weights into bf16 hi/lo fragment order ----------
__global__ void __launch_bounds__(256)
pack_weights(const float* __restrict__ W1, const float* __restrict__ W2)
{
    const int t = blockIdx.x * 256 + threadIdx.x;   // 0..16383
    const int half = t >> 13;
    const int u = t & 8191;
    const int lane = u & 31;
    const int grp  = lane >> 2;
    const int tig  = lane & 3;

    uint4 v;
    if (half == 0) {
        const int q  = (u >> 5) & 3;
        const int kt = (u >> 7) & 3;
        const int c  = u >> 9;
        const bool lo_sel = q >= 2;
        const int ntA = (q & 1) * 2;
        #pragma unroll
        for (int j = 0; j < 2; j++) {
            const int nt = ntA + j;
            const int g  = nt * 8 + grp;
            const float* wr = W1 + ((size_t)c * Gg + g) * Dd + kt * 16 + 2 * tig;
            uint32_t h0, l0, h1, l1;
            split_pair(wr[0], wr[1], h0, l0);       // b0: k = 2tig, 2tig+1
            split_pair(wr[8], wr[9], h1, l1);       // b1: k = 2tig+8, 2tig+9
            if (j == 0) { v.x = lo_sel ? l0 : h0; v.y = lo_sel ? l1 : h1; }
            else        { v.z = lo_sel ? l0 : h0; v.w = lo_sel ? l1 : h1; }
        }
        W1pk[u] = v;
    } else {
        const int hl = (u >> 5) & 1;
        const int nt = (u >> 6) & 7;
        const int c  = u >> 9;
        const int d  = nt * 8 + grp;
        #pragma unroll
        for (int kt = 0; kt < 2; kt++) {
            const float* wr = W2 + ((size_t)c * Dd + d) * Gg + kt * 16 + 2 * tig;
            uint32_t h0, l0, h1, l1;
            split_pair(wr[0], wr[1], h0, l0);
            split_pair(wr[8], wr[9], h1, l1);
            uint32_t e0 = hl ? l0 : h0, e1 = hl ? l1 : h1;
            if (kt == 0) { v.x = e0; v.y = e1; }
            else         { v.z = e0; v.w = e1; }
        }
        W2pk[u] = v;
    }
}

extern __shared__ char smem_raw[];
// [0, 147456): two m tile buffers (uint2 (hi,lo) bf16 pairs); [147456,+1K): A_s

__global__ void __launch_bounds__(NTH, 1)
causal_dag_kernel(const float* __restrict__ x,  const float* __restrict__ A,
                  const float* __restrict__ b1, const float* __restrict__ b2,
                  float* __restrict__ out, int nTiles)
{
    uint2* mbuf = (uint2*)smem_raw;
    float* A_s  = (float*)(smem_raw + 2 * TILEU2 * 8);
    const int tid = threadIdx.x;

    if (tid < 256) A_s[tid] = A[tid];
    __syncthreads();

    // ---- mix role: warp = batch row, lane = float2 chunk of D ---------------
    const int bl = tid >> 5;              // 0..15 local batch row
    // ---- mlp role: warp = concept -------------------------------------------
    const int c    = tid >> 5;            // warp id == concept
    const int lane = tid & 31;
    const int grp  = lane >> 2;
    const int tig  = lane & 3;

    int prev_b0 = 0;
    int have_prev = 0;
    int par = 0;

    for (int t = blockIdx.x; t < nTiles + 0; t += gridDim.x) {
        // =================== MIX: tile t -> mbuf[par] ========================
        {
            uint2* buf = mbuf + par * TILEU2;
            const ull* xb = (const ull*)(x + (size_t)(t * 16 + bl) * (Cc * Dd)) + lane;
            ull mr[Cc];
            #pragma unroll
            for (int i = 0; i < Cc; i++) mr[i] = 0ull;
            #pragma unroll
            for (int j = 0; j < Cc; j++) {
                ull xv = __ldcs(xb + j * 32);     // streaming: keep weights in L1
                const float4* ar = (const float4*)(A_s + j * Cc);
                #pragma unroll
                for (int i4 = 0; i4 < 4; i4++) {
                    float4 av = ar[i4];           // 1 LDS.128 = 4 A values
                    float a4[4] = {av.x, av.y, av.z, av.w};
                    #pragma unroll
                    for (int ii = 0; ii < 4; ii++)
                        mr[i4 * 4 + ii] = fma2(dup2(a4[ii]), xv, mr[i4 * 4 + ii]);
                }
            }
            #pragma unroll
            for (int i = 0; i < Cc; i++) {
                float f0, f1;
                asm("mov.b64 {%0, %1}, %2;" : "=f"(f0), "=f"(f1) : "l"(mr[i]));
                uint2 v;
                split_pair(f0, f1, v.x, v.y);     // {hi, lo} of pair 'lane'
                buf[(i * 16 + bl) * ROWU2 + lane] = v;
            }
        }

        // =================== MLP: tile t-1 from mbuf[par^1] ==================
        if (have_prev) {
            const uint2* mc = mbuf + (par ^ 1) * TILEU2 + c * CTU2;

            // ---- Phase 2: H[16x32] = elu(M @ W1_c^T + b1) ----
            float acc[4][4];
            #pragma unroll
            for (int nt = 0; nt < 4; nt++)
                #pragma unroll
                for (int q = 0; q < 4; q++) acc[nt][q] = 0.0f;

            #pragma unroll
            for (int kt = 0; kt < 4; kt++) {
                const int pi = kt * 8 + tig;
                const uint2 a0 = mc[grp * ROWU2 + pi];
                const uint2 a1 = mc[(grp + 8) * ROWU2 + pi];
                const uint2 a2 = mc[grp * ROWU2 + pi + 4];
                const uint2 a3 = mc[(grp + 8) * ROWU2 + pi + 4];
                const int wb = ((c * 4 + kt) * 4) * 32 + lane;
                const uint4 q0 = W1pk[wb];
                const uint4 q1 = W1pk[wb + 32];
                const uint4 q2 = W1pk[wb + 64];
                const uint4 q3 = W1pk[wb + 96];
                // nt0
                mma_bf16(acc[0], a0.x, a1.x, a2.x, a3.x, q0.x, q0.y);
                mma_bf16(acc[0], a0.y, a1.y, a2.y, a3.y, q0.x, q0.y);
                mma_bf16(acc[0], a0.x, a1.x, a2.x, a3.x, q2.x, q2.y);
                // nt1
                mma_bf16(acc[1], a0.x, a1.x, a2.x, a3.x, q0.z, q0.w);
                mma_bf16(acc[1], a0.y, a1.y, a2.y, a3.y, q0.z, q0.w);
                mma_bf16(acc[1], a0.x, a1.x, a2.x, a3.x, q2.z, q2.w);
                // nt2
                mma_bf16(acc[2], a0.x, a1.x, a2.x, a3.x, q1.x, q1.y);
                mma_bf16(acc[2], a0.y, a1.y, a2.y, a3.y, q1.x, q1.y);
                mma_bf16(acc[2], a0.x, a1.x, a2.x, a3.x, q3.x, q3.y);
                // nt3
                mma_bf16(acc[3], a0.x, a1.x, a2.x, a3.x, q1.z, q1.w);
                mma_bf16(acc[3], a0.y, a1.y, a2.y, a3.y, q1.z, q1.w);
                mma_bf16(acc[3], a0.x, a1.x, a2.x, a3.x, q3.z, q3.w);
            }
            // bias + ELU + split to bf16 hi/lo (phase-3 A fragments, registers)
            uint32_t hfh[8], hfl[8];
            #pragma unroll
            for (int nt = 0; nt < 4; nt++) {
                const float2 bias = *(const float2*)&b1[c * Gg + nt * 8 + 2 * tig];
                float v0 = elu1(acc[nt][0] + bias.x);
                float v1 = elu1(acc[nt][1] + bias.y);
                float v2 = elu1(acc[nt][2] + bias.x);
                float v3 = elu1(acc[nt][3] + bias.y);
                split_pair(v0, v1, hfh[2 * nt],     hfl[2 * nt]);
                split_pair(v2, v3, hfh[2 * nt + 1], hfl[2 * nt + 1]);
            }

            // ---- Phase 3: Out = H @ W2_c^T + b2 (registers only) ----
            #pragma unroll
            for (int nt = 0; nt < 8; nt++) {
                const int wb = ((c * 8 + nt) * 2) * 32 + lane;
                const uint4 gh = W2pk[wb];
                const uint4 gl = W2pk[wb + 32];
                const float2 bias = *(const float2*)&b2[c * Dd + nt * 8 + 2 * tig];
                float o[4] = {0.0f, 0.0f, 0.0f, 0.0f};
                // kt'=0
                mma_bf16(o, hfh[0], hfh[1], hfh[2], hfh[3], gh.x, gh.y);
                mma_bf16(o, hfl[0], hfl[1], hfl[2], hfl[3], gh.x, gh.y);
                mma_bf16(o, hfh[0], hfh[1], hfh[2], hfh[3], gl.x, gl.y);
                // kt'=1
                mma_bf16(o, hfh[4], hfh[5], hfh[6], hfh[7], gh.z, gh.w);
                mma_bf16(o, hfl[4], hfl[5], hfl[6], hfl[7], gh.z, gh.w);
                mma_bf16(o, hfh[4], hfh[5], hfh[6], hfh[7], gl.z, gl.w);

                float2 v0; v0.x = o[0] + bias.x; v0.y = o[1] + bias.y;
                float2 v1; v1.x = o[2] + bias.x; v1.y = o[3] + bias.y;
                __stcs((float2*)(out + ((size_t)(prev_b0 + grp) * Cc + c) * Dd
                                     + nt * 8 + 2 * tig), v0);
                __stcs((float2*)(out + ((size_t)(prev_b0 + grp + 8) * Cc + c) * Dd
                                     + nt * 8 + 2 * tig), v1);
            }
        }

        __syncthreads();
        prev_b0 = t * 16;
        have_prev = 1;
        par ^= 1;
    }

    // =================== Epilogue: MLP for the last mixed tile ===============
    if (have_prev) {
        const uint2* mc = mbuf + (par ^ 1) * TILEU2 + c * CTU2;

        float acc[4][4];
        #pragma unroll
        for (int nt = 0; nt < 4; nt++)
            #pragma unroll
            for (int q = 0; q < 4; q++) acc[nt][q] = 0.0f;

        #pragma unroll
        for (int kt = 0; kt < 4; kt++) {
            const int pi = kt * 8 + tig;
            const uint2 a0 = mc[grp * ROWU2 + pi];
            const uint2 a1 = mc[(grp + 8) * ROWU2 + pi];
            const uint2 a2 = mc[grp * ROWU2 + pi + 4];
            const uint2 a3 = mc[(grp + 8) * ROWU2 + pi + 4];
            const int wb = ((c * 4 + kt) * 4) * 32 + lane;
            const uint4 q0 = W1pk[wb];
            const uint4 q1 = W1pk[wb + 32];
            const uint4 q2 = W1pk[wb + 64];
            const uint4 q3 = W1pk[wb + 96];
            mma_bf16(acc[0], a0.x, a1.x, a2.x, a3.x, q0.x, q0.y);
            mma_bf16(acc[0], a0.y, a1.y, a2.y, a3.y, q0.x, q0.y);
            mma_bf16(acc[0], a0.x, a1.x, a2.x, a3.x, q2.x, q2.y);
            mma_bf16(acc[1], a0.x, a1.x, a2.x, a3.x, q0.z, q0.w);
            mma_bf16(acc[1], a0.y, a1.y, a2.y, a3.y, q0.z, q0.w);
            mma_bf16(acc[1], a0.x, a1.x, a2.x, a3.x, q2.z, q2.w);
            mma_bf16(acc[2], a0.x, a1.x, a2.x, a3.x, q1.x, q1.y);
            mma_bf16(acc[2], a0.y, a1.y, a2.y, a3.y, q1.x, q1.y);
            mma_bf16(acc[2], a0.x, a1.x, a2.x, a3.x, q3.x, q3.y);
            mma_bf16(acc[3], a0.x, a1.x, a2.x, a3.x, q1.z, q1.w);
            mma_bf16(acc[3], a0.y, a1.y, a2.y, a3.y, q1.z, q1.w);
            mma_bf16(acc[3], a0.x, a1.x, a2.x, a3.x, q3.z, q3.w);
        }
        uint32_t hfh[8], hfl[8];
        #pragma unroll
        for (int nt = 0; nt < 4; nt++) {
            const float2 bias = *(const float2*)&b1[c * Gg + nt * 8 + 2 * tig];
            float v0 = elu1(acc[nt][0] + bias.x);
            float v1 = elu1(acc[nt][1] + bias.y);
            float v2 = elu1(acc[nt][2] + bias.x);
            float v3 = elu1(acc[nt][3] + bias.y);
            split_pair(v0, v1, hfh[2 * nt],     hfl[2 * nt]);
            split_pair(v2, v3, hfh[2 * nt + 1], hfl[2 * nt + 1]);
        }
        #pragma unroll
        for (int nt = 0; nt < 8; nt++) {
            const int wb = ((c * 8 + nt) * 2) * 32 + lane;
            const uint4 gh = W2pk[wb];
            const uint4 gl = W2pk[wb + 32];
            const float2 bias = *(const float2*)&b2[c * Dd + nt * 8 + 2 * tig];
            float o[4] = {0.0f, 0.0f, 0.0f, 0.0f};
            mma_bf16(o, hfh[0], hfh[1], hfh[2], hfh[3], gh.x, gh.y);
            mma_bf16(o, hfl[0], hfl[1], hfl[2], hfl[3], gh.x, gh.y);
            mma_bf16(o, hfh[0], hfh[1], hfh[2], hfh[3], gl.x, gl.y);
            mma_bf16(o, hfh[4], hfh[5], hfh[6], hfh[7], gh.z, gh.w);
            mma_bf16(o, hfl[4], hfl[5], hfl[6], hfl[7], gh.z, gh.w);
            mma_bf16(o, hfh[4], hfh[5], hfh[6], hfh[7], gl.z, gl.w);

            float2 v0; v0.x = o[0] + bias.x; v0.y = o[1] + bias.y;
            float2 v1; v1.x = o[2] + bias.x; v1.y = o[3] + bias.y;
            __stcs((float2*)(out + ((size_t)(prev_b0 + grp) * Cc + c) * Dd
                                 + nt * 8 + 2 * tig), v0);
            __stcs((float2*)(out + ((size_t)(prev_b0 + grp + 8) * Cc + c) * Dd
                                 + nt * 8 + 2 * tig), v1);
        }
    }
}

extern "C" void kernel_launch(void* const* d_in, const int* in_sizes, int n_in,
                              void* d_out, int out_size)
{
    const float* x  = (const float*)d_in[0];
    const float* A  = (const float*)d_in[1];
    const float* W1 = (const float*)d_in[2];
    const float* b1 = (const float*)d_in[3];
    const float* W2 = (const float*)d_in[4];
    const float* b2 = (const float*)d_in[5];
    float* out = (float*)d_out;

    const int Btot   = in_sizes[0] / (Cc * Dd);        // 65536
    const int nTiles = Btot / 16;                      // 4096

    int sms = 148;
    cudaDeviceGetAttribute(&sms, cudaDevAttrMultiProcessorCount, 0);

    const int smem_bytes = 2 * TILEU2 * 8 + 1024;      // 148480 B

    pack_weights<<<64, 256>>>(W1, W2);

    cudaFuncSetAttribute(causal_dag_kernel,
                         cudaFuncAttributeMaxDynamicSharedMemorySize, smem_bytes);
    causal_dag_kernel<<<sms, NTH, smem_bytes>>>(x, A, b1, b2, out, nTiles);
}

// round 14
// speedup vs baseline: 1.0799x; 1.0799x over previous
#include <cuda_runtime.h>
#include <cstdint>

// CausalDAG fused kernel for GB300 (sm_103a). R13.
//   m = A^T x (exact fp32 fma2, emitted as bf16 hi/lo pairs)
//   h = elu(W1_c @ m + b1); out = W2_c @ h + b2   (bf16 m16n8k16, 3-mma comp)
//
// vs R8/R12: CTA shrunk to 256 threads / ONE 16-row tile, grid = 4096.
// smem = 74.8 KB/CTA -> 2 CTAs resident per SM (32 warps vs 16): independent
// co-resident CTAs cover each other's barrier/latency stalls, attacking the
// issue=33% wall that every 512-thread variant hit (RF-capped at 16 warps).

#define Cc 16
#define Dd 64
#define Gg 32
#define NTH 256
#define ROWU2 36            // uint2 (hi,lo) pairs per row incl. pad
#define CTU2 (16 * ROWU2)   // uint2 per concept block = 576
#define TILEU2 (Cc * CTU2)  // 9216 uint2 = 73728 B

typedef unsigned long long ull;

// Prepacked bf16 hi/lo weight fragments (same layout as R8).
// W1pk[((c*4+kt)*4+q)*32+lane], q: 0=hi(nt0,nt1) 1=hi(nt2,nt3) 2=lo(nt0,nt1) 3=lo(nt2,nt3)
// W2pk[((c*8+nt)*2+hl)*32+lane], uint4 = {b0(kt0),b1(kt0),b0(kt1),b1(kt1)}
__device__ uint4 W1pk[Cc * 4 * 4 * 32];
__device__ uint4 W2pk[Cc * 8 * 2 * 32];

__device__ __forceinline__ ull fma2(ull a, ull b, ull c) {
    ull d;
    asm("fma.rn.f32x2 %0, %1, %2, %3;" : "=l"(d) : "l"(a), "l"(b), "l"(c));
    return d;
}
__device__ __forceinline__ ull dup2(float a) {
    ull d;
    asm("mov.b64 %0, {%1, %1};" : "=l"(d) : "f"(a));
    return d;
}
// pack two f32 -> bf16x2, first arg lands in lower 16 bits
__device__ __forceinline__ uint32_t pack_bf16_2(float lo, float hi) {
    uint32_t r;
    asm("cvt.rn.bf16x2.f32 %0, %1, %2;" : "=r"(r) : "f"(hi), "f"(lo));
    return r;
}
// fp32 pair -> bf16 hi pair + bf16 lo pair (residual)
__device__ __forceinline__ void split_pair(float f0, float f1,
                                           uint32_t& hi, uint32_t& lo) {
    hi = pack_bf16_2(f0, f1);
    float f0h = __uint_as_float(hi << 16);
    float f1h = __uint_as_float(hi & 0xffff0000u);
    lo = pack_bf16_2(f0 - f0h, f1 - f1h);
}
__device__ __forceinline__ void mma_bf16(float c[4],
                                         uint32_t a0, uint32_t a1, uint32_t a2, uint32_t a3,
                                         uint32_t b0, uint32_t b1) {
    asm volatile(
        "mma.sync.aligned.m16n8k16.row.col.f32.bf16.bf16.f32 "
        "{%0,%1,%2,%3}, {%4,%5,%6,%7}, {%8,%9}, {%0,%1,%2,%3};"
        : "+f"(c[0]), "+f"(c[1]), "+f"(c[2]), "+f"(c[3])
        : "r"(a0), "r"(a1), "r"(a2), "r"(a3), "r"(b0), "r"(b1));
}
__device__ __forceinline__ float elu1(float v) {
    return v > 0.0f ? v : (__expf(v) - 1.0f);
}

// ---------------- Prep: pack weights into bf16 hi/lo fragment order ----------
__global__ void __launch_bounds__(256)
pack_weights(const float* __restrict__ W1, const float* __restrict__ W2)
{
    const int t = blockIdx.x * 256 + threadIdx.x;   // 0..16383
    const int half = t >> 13;
    const int u = t & 8191;
    const int lane = u & 31;
    const int grp  = lane >> 2;
    const int tig  = lane & 3;

    uint4 v;
    if (half == 0) {
        const int q  = (u >> 5) & 3;
        const int kt = (u >> 7) & 3;
        const int c  = u >> 9;
        const bool lo_sel = q >= 2;
        const int ntA = (q & 1) * 2;
        #pragma unroll
        for (int j = 0; j < 2; j++) {
            const int nt = ntA + j;
            const int g  = nt * 8 + grp;
            const float* wr = W1 + ((size_t)c * Gg + g) * Dd + kt * 16 + 2 * tig;
            uint32_t h0, l0, h1, l1;
            split_pair(wr[0], wr[1], h0, l0);       // b0: k = 2tig, 2tig+1
            split_pair(wr[8], wr[9], h1, l1);       // b1: k = 2tig+8, 2tig+9
            if (j == 0) { v.x = lo_sel ? l0 : h0; v.y = lo_sel ? l1 : h1; }
            else        { v.z = lo_sel ? l0 : h0; v.w = lo_sel ? l1 : h1; }
        }
        W1pk[u] = v;
    } else {
        const int hl = (u >> 5) & 1;
        const int nt = (u >> 6) & 7;
        const int c  = u >> 9;
        const int d  = nt * 8 + grp;
        #pragma unroll
        for (int kt = 0; kt < 2; kt++) {
            const float* wr = W2 + ((size_t)c * Dd + d) * Gg + kt * 16 + 2 * tig;
            uint32_t h0, l0, h1, l1;
            split_pair(wr[0], wr[1], h0, l0);
            split_pair(wr[8], wr[9], h1, l1);
            uint32_t e0 = hl ? l0 : h0, e1 = hl ? l1 : h1;
            if (kt == 0) { v.x = e0; v.y = e1; }
            else         { v.z = e0; v.w = e1; }
        }
        W2pk[u] = v;
    }
}

extern __shared__ char smem_raw[];
// [0, 73728): m tile buffer (uint2 (hi,lo) bf16 pairs); [73728, 74752): A_s

__global__ void __launch_bounds__(NTH, 2)
causal_dag_kernel(const float* __restrict__ x,  const float* __restrict__ A,
                  const float* __restrict__ b1, const float* __restrict__ b2,
                  float* __restrict__ out)
{
    uint2* mbuf = (uint2*)smem_raw;
    float* A_s  = (float*)(smem_raw + TILEU2 * 8);
    const int tid = threadIdx.x;
    const int b0  = blockIdx.x * 16;

    A_s[tid] = A[tid];                     // 256 threads == C*C elements
    __syncthreads();

    // =================== MIX: m[c][bl][d] -> smem (bf16 hi/lo) ===============
    {
        const int bl = tid >> 4;           // 0..15 local batch row
        const int dq = tid & 15;           // float4 chunk of D=64
        const ulonglong2* xb =
            (const ulonglong2*)(x + (size_t)(b0 + bl) * (Cc * Dd)) + dq;

        ull mrx[Cc], mrz[Cc];
        #pragma unroll
        for (int i = 0; i < Cc; i++) { mrx[i] = 0ull; mrz[i] = 0ull; }
        #pragma unroll
        for (int j = 0; j < Cc; j++) {
            ulonglong2 xv;
            {   // streaming load: keep weight set L1-resident
                const float4 f = __ldcs((const float4*)(xb + j * 16));
                asm("mov.b64 %0, {%2, %3}; mov.b64 %1, {%4, %5};"
                    : "=l"(xv.x), "=l"(xv.y)
                    : "f"(f.x), "f"(f.y), "f"(f.z), "f"(f.w));
            }
            const float4* ar = (const float4*)(A_s + j * Cc);
            #pragma unroll
            for (int i4 = 0; i4 < 4; i4++) {
                float4 av = ar[i4];        // 1 LDS.128 = 4 A values
                float a4[4] = {av.x, av.y, av.z, av.w};
                #pragma unroll
                for (int ii = 0; ii < 4; ii++) {
                    ull a2 = dup2(a4[ii]);
                    mrx[i4 * 4 + ii] = fma2(a2, xv.x, mrx[i4 * 4 + ii]);
                    mrz[i4 * 4 + ii] = fma2(a2, xv.y, mrz[i4 * 4 + ii]);
                }
            }
        }
        #pragma unroll
        for (int i = 0; i < Cc; i++) {
            float f0, f1, g0, g1;
            asm("mov.b64 {%0, %1}, %2;" : "=f"(f0), "=f"(f1) : "l"(mrx[i]));
            asm("mov.b64 {%0, %1}, %2;" : "=f"(g0), "=f"(g1) : "l"(mrz[i]));
            uint4 v;
            split_pair(f0, f1, v.x, v.y);  // pair 2dq   : {hi, lo}
            split_pair(g0, g1, v.z, v.w);  // pair 2dq+1 : {hi, lo}
            *(uint4*)&mbuf[(i * 16 + bl) * ROWU2 + 2 * dq] = v;
        }
    }
    __syncthreads();

    // =================== MLP: warp = concepts 2w, 2w+1 =======================
    const int w    = tid >> 5;             // 0..7
    const int lane = tid & 31;
    const int grp  = lane >> 2;
    const int tig  = lane & 3;

    #pragma unroll
    for (int s = 0; s < 2; s++) {
        const int c = 2 * w + s;
        const uint2* mc = mbuf + c * CTU2;

        // ---- Phase 2: H[16x32] = elu(M @ W1_c^T + b1) ----
        float acc[4][4];
        #pragma unroll
        for (int nt = 0; nt < 4; nt++)
            #pragma unroll
            for (int q = 0; q < 4; q++) acc[nt][q] = 0.0f;

        #pragma unroll
        for (int kt = 0; kt < 4; kt++) {
            const int pi = kt * 8 + tig;
            const uint2 a0 = mc[grp * ROWU2 + pi];
            const uint2 a1 = mc[(grp + 8) * ROWU2 + pi];
            const uint2 a2 = mc[grp * ROWU2 + pi + 4];
            const uint2 a3 = mc[(grp + 8) * ROWU2 + pi + 4];
            const int wb = ((c * 4 + kt) * 4) * 32 + lane;
            const uint4 q0 = W1pk[wb];
            const uint4 q1 = W1pk[wb + 32];
            const uint4 q2 = W1pk[wb + 64];
            const uint4 q3 = W1pk[wb + 96];
            // nt0
            mma_bf16(acc[0], a0.x, a1.x, a2.x, a3.x, q0.x, q0.y);
            mma_bf16(acc[0], a0.y, a1.y, a2.y, a3.y, q0.x, q0.y);
            mma_bf16(acc[0], a0.x, a1.x, a2.x, a3.x, q2.x, q2.y);
            // nt1
            mma_bf16(acc[1], a0.x, a1.x, a2.x, a3.x, q0.z, q0.w);
            mma_bf16(acc[1], a0.y, a1.y, a2.y, a3.y, q0.z, q0.w);
            mma_bf16(acc[1], a0.x, a1.x, a2.x, a3.x, q2.z, q2.w);
            // nt2
            mma_bf16(acc[2], a0.x, a1.x, a2.x, a3.x, q1.x, q1.y);
            mma_bf16(acc[2], a0.y, a1.y, a2.y, a3.y, q1.x, q1.y);
            mma_bf16(acc[2], a0.x, a1.x, a2.x, a3.x, q3.x, q3.y);
            // nt3
            mma_bf16(acc[3], a0.x, a1.x, a2.x, a3.x, q1.z, q1.w);
            mma_bf16(acc[3], a0.y, a1.y, a2.y, a3.y, q1.z, q1.w);
            mma_bf16(acc[3], a0.x, a1.x, a2.x, a3.x, q3.z, q3.w);
        }

        // bias + ELU + split to bf16 hi/lo (phase-3 A fragments, registers)
        uint32_t hfh[8], hfl[8];
        #pragma unroll
        for (int nt = 0; nt < 4; nt++) {
            const float2 bias = *(const float2*)&b1[c * Gg + nt * 8 + 2 * tig];
            float v0 = elu1(acc[nt][0] + bias.x);
            float v1 = elu1(acc[nt][1] + bias.y);
            float v2 = elu1(acc[nt][2] + bias.x);
            float v3 = elu1(acc[nt][3] + bias.y);
            split_pair(v0, v1, hfh[2 * nt],     hfl[2 * nt]);
            split_pair(v2, v3, hfh[2 * nt + 1], hfl[2 * nt + 1]);
        }

        // ---- Phase 3: Out[16x64] = H @ W2_c^T + b2 (registers only) ----
        #pragma unroll
        for (int nt = 0; nt < 8; nt++) {
            const int wb = ((c * 8 + nt) * 2) * 32 + lane;
            const uint4 gh = W2pk[wb];
            const uint4 gl = W2pk[wb + 32];
            const float2 bias = *(const float2*)&b2[c * Dd + nt * 8 + 2 * tig];
            float o[4] = {0.0f, 0.0f, 0.0f, 0.0f};
            // kt'=0
            mma_bf16(o, hfh[0], hfh[1], hfh[2], hfh[3], gh.x, gh.y);
            mma_bf16(o, hfl[0], hfl[1], hfl[2], hfl[3], gh.x, gh.y);
            mma_bf16(o, hfh[0], hfh[1], hfh[2], hfh[3], gl.x, gl.y);
            // kt'=1
            mma_bf16(o, hfh[4], hfh[5], hfh[6], hfh[7], gh.z, gh.w);
            mma_bf16(o, hfl[4], hfl[5], hfl[6], hfl[7], gh.z, gh.w);
            mma_bf16(o, hfh[4], hfh[5], hfh[6], hfh[7], gl.z, gl.w);

            float2 v0; v0.x = o[0] + bias.x; v0.y = o[1] + bias.y;
            float2 v1; v1.x = o[2] + bias.x; v1.y = o[3] + bias.y;
            __stcs((float2*)(out + ((size_t)(b0 + grp) * Cc + c) * Dd
                                 + nt * 8 + 2 * tig), v0);
            __stcs((float2*)(out + ((size_t)(b0 + grp + 8) * Cc + c) * Dd
                                 + nt * 8 + 2 * tig), v1);
        }
    }
}

extern "C" void kernel_launch(void* const* d_in, const int* in_sizes, int n_in,
                              void* d_out, int out_size)
{
    const float* x  = (const float*)d_in[0];
    const float* A  = (const float*)d_in[1];
    const float* W1 = (const float*)d_in[2];
    const float* b1 = (const float*)d_in[3];
    const float* W2 = (const float*)d_in[4];
    const float* b2 = (const float*)d_in[5];
    float* out = (float*)d_out;

    const int Btot   = in_sizes[0] / (Cc * Dd);        // 65536
    const int nTiles = Btot / 16;                      // 4096

    const int smem_bytes = TILEU2 * 8 + 1024;          // 74752 B

    pack_weights<<<64, 256>>>(W1, W2);

    cudaFuncSetAttribute(causal_dag_kernel,
                         cudaFuncAttributeMaxDynamicSharedMemorySize, smem_bytes);
    causal_dag_kernel<<<nTiles, NTH, smem_bytes>>>(x, A, b1, b2, out);
}